// round 1
// baseline (speedup 1.0000x reference)
#include <cuda_runtime.h>
#include <cstdint>

// ---------------------------------------------------------------------------
// DenseGCN (3-layer GraphSAGE, mean aggr) on GB300.
// Strategy:
//   - mean-aggregation commutes with the linear map => matmul FIRST, then
//     aggregate (layer3 gather shrinks 256->128 floats/edge).
//   - CSR build per launch (histogram + scan + scatter) => gather-side
//     aggregation, no float atomics.
//   - fused concatenated GEMMs: x@[Wl|Wr] per layer.
// Layout of feature buffer g_F[N][256]: cols 0:64 = x_p, 64:128 = h1,
// 128:256 = h2. in2 = F[:,0:128], in3 = F[:,0:256].
// ---------------------------------------------------------------------------

#define NMAX 50176
#define EMAX 1000448

__device__ __align__(16) float g_F[(size_t)NMAX * 256];
__device__ __align__(16) float g_Y[(size_t)NMAX * 256];
__device__ __align__(16) float g_Wcat[256 * 256];
__device__ int g_row_off[NMAX + 1];
__device__ int g_cnt[NMAX];
__device__ int g_src_sorted[EMAX];
__device__ int g_is64;

// --------------------------- edge dtype detection --------------------------
__global__ void detect_kernel(const unsigned int* e) {
    if (threadIdx.x == 0) {
        int is64 = 1;
        for (int i = 0; i < 8; i++)
            if (e[2 * i + 1] != 0u) is64 = 0;  // high word of int64 elems
        g_is64 = is64;
    }
}

__global__ void zero_cnt(int n) {
    int i = blockIdx.x * blockDim.x + threadIdx.x;
    if (i < n) g_cnt[i] = 0;
}

__global__ void hist_kernel(const void* e, int E) {
    int i = blockIdx.x * blockDim.x + threadIdx.x;
    if (i >= E) return;
    int dst;
    if (g_is64) dst = (int)((const long long*)e)[(size_t)E + i];
    else        dst = ((const int*)e)[E + i];
    atomicAdd(&g_cnt[dst], 1);
}

// single-block exclusive scan: g_cnt (counts) -> g_row_off; g_cnt becomes cursor
__global__ void scan_kernel(int n) {
    __shared__ int sh[1024];
    __shared__ int carry;
    int tid = threadIdx.x;
    if (tid == 0) carry = 0;
    __syncthreads();
    for (int base = 0; base < n; base += 1024) {
        int i = base + tid;
        int v = (i < n) ? g_cnt[i] : 0;
        sh[tid] = v;
        __syncthreads();
        for (int off = 1; off < 1024; off <<= 1) {
            int t = (tid >= off) ? sh[tid - off] : 0;
            __syncthreads();
            sh[tid] += t;
            __syncthreads();
        }
        int excl = carry + sh[tid] - v;
        if (i < n) { g_row_off[i] = excl; g_cnt[i] = excl; }
        __syncthreads();
        if (tid == 0) carry += sh[1023];
        __syncthreads();
    }
    if (tid == 0) g_row_off[n] = carry;  // == E
}

__global__ void scatter_kernel(const void* e, int E) {
    int i = blockIdx.x * blockDim.x + threadIdx.x;
    if (i >= E) return;
    int src, dst;
    if (g_is64) {
        src = (int)((const long long*)e)[i];
        dst = (int)((const long long*)e)[(size_t)E + i];
    } else {
        src = ((const int*)e)[i];
        dst = ((const int*)e)[E + i];
    }
    int pos = atomicAdd(&g_cnt[dst], 1);
    g_src_sorted[pos] = src;
}

// pack [Wl | Wr] -> g_Wcat  ([K, 2*Fo] row-major)
__global__ void pack2_kernel(const float* __restrict__ Wl,
                             const float* __restrict__ Wr, int K, int Fo) {
    int i = blockIdx.x * blockDim.x + threadIdx.x;
    if (i >= K * Fo) return;
    int k = i / Fo, n = i % Fo;
    g_Wcat[k * (2 * Fo) + n]      = Wl[i];
    g_Wcat[k * (2 * Fo) + Fo + n] = Wr[i];
}

// --------------------------------- SGEMM -----------------------------------
// C[M,N] (+bias, +relu) = A[M,K] @ B[K,N].  64x64 tile, 4x4 micro-tile.
__global__ void __launch_bounds__(256) sgemm_kernel(
    const float* __restrict__ A, int lda,
    const float* __restrict__ B,          // [K,N] row-major, contiguous
    const float* __restrict__ bias,       // len N or nullptr
    float* __restrict__ C, int ldc, int coff,
    int M, int N, int K, int do_relu)
{
    __shared__ float As[16][68];   // transposed A tile (k-major), padded
    __shared__ float Bs[16][68];
    int tid = threadIdx.x;
    int tx = tid & 15, ty = tid >> 4;
    int m0 = blockIdx.x << 6, n0 = blockIdx.y << 6;
    float acc[4][4];
#pragma unroll
    for (int i = 0; i < 4; i++)
#pragma unroll
        for (int j = 0; j < 4; j++) acc[i][j] = 0.f;

    int ar = tid >> 2;            // 0..63  (m within tile)
    int ac = (tid & 3) << 2;      // 0,4,8,12 (k within tile)
    int br = tid >> 4;            // 0..15  (k within tile)
    int bc = (tid & 15) << 2;     // 0..60  (n within tile)
    int am = m0 + ar;

    for (int k0 = 0; k0 < K; k0 += 16) {
        float4 a4 = make_float4(0.f, 0.f, 0.f, 0.f);
        if (am < M) a4 = *(const float4*)&A[(size_t)am * lda + k0 + ac];
        As[ac + 0][ar] = a4.x; As[ac + 1][ar] = a4.y;
        As[ac + 2][ar] = a4.z; As[ac + 3][ar] = a4.w;
        float4 b4 = *(const float4*)&B[(size_t)(k0 + br) * N + n0 + bc];
        *(float4*)&Bs[br][bc] = b4;
        __syncthreads();
#pragma unroll
        for (int k = 0; k < 16; k++) {
            float4 a = *(float4*)&As[k][ty << 2];
            float4 b = *(float4*)&Bs[k][tx << 2];
            acc[0][0] += a.x * b.x; acc[0][1] += a.x * b.y;
            acc[0][2] += a.x * b.z; acc[0][3] += a.x * b.w;
            acc[1][0] += a.y * b.x; acc[1][1] += a.y * b.y;
            acc[1][2] += a.y * b.z; acc[1][3] += a.y * b.w;
            acc[2][0] += a.z * b.x; acc[2][1] += a.z * b.y;
            acc[2][2] += a.z * b.z; acc[2][3] += a.z * b.w;
            acc[3][0] += a.w * b.x; acc[3][1] += a.w * b.y;
            acc[3][2] += a.w * b.z; acc[3][3] += a.w * b.w;
        }
        __syncthreads();
    }
    float4 bb = make_float4(0.f, 0.f, 0.f, 0.f);
    if (bias) bb = *(const float4*)&bias[n0 + (tx << 2)];
#pragma unroll
    for (int i = 0; i < 4; i++) {
        int m = m0 + (ty << 2) + i;
        if (m < M) {
            float4 v;
            v.x = acc[i][0] + bb.x; v.y = acc[i][1] + bb.y;
            v.z = acc[i][2] + bb.z; v.w = acc[i][3] + bb.w;
            if (do_relu) {
                v.x = fmaxf(v.x, 0.f); v.y = fmaxf(v.y, 0.f);
                v.z = fmaxf(v.z, 0.f); v.w = fmaxf(v.w, 0.f);
            }
            *(float4*)&C[(size_t)m * ldc + coff + n0 + (tx << 2)] = v;
        }
    }
}

// ------------------------------ aggregation --------------------------------
// out[n] = relu( mean_j Y[src_j, ycol:ycol+F] + Y[n, rcol:rcol+F] + bias )
// One warp per node; lane handles V floats (V = F/32).
template <int V>
__global__ void agg_kernel(const float* __restrict__ Y, int ldy, int ycol,
                           int rcol, const float* __restrict__ bias,
                           float* __restrict__ Out, int ldo, int ocol, int Nn)
{
    int gw = (blockIdx.x * blockDim.x + threadIdx.x) >> 5;
    int lane = threadIdx.x & 31;
    if (gw >= Nn) return;
    int s0 = g_row_off[gw], s1 = g_row_off[gw + 1];
    int col = lane * V;
    float acc[V];
#pragma unroll
    for (int v = 0; v < V; v++) acc[v] = 0.f;
    const float* Yb = Y + ycol + col;

    int j = s0;
    for (; j + 1 < s1; j += 2) {   // 2-way unroll for MLP
        int sA = g_src_sorted[j];
        int sB = g_src_sorted[j + 1];
        const float* pA = Yb + (size_t)sA * ldy;
        const float* pB = Yb + (size_t)sB * ldy;
        if (V == 4) {
            float4 a = *(const float4*)pA;
            float4 b = *(const float4*)pB;
            acc[0] += a.x + b.x; acc[1] += a.y + b.y;
            acc[2] += a.z + b.z; acc[3] += a.w + b.w;
        } else {
            float2 a = *(const float2*)pA;
            float2 b = *(const float2*)pB;
            acc[0] += a.x + b.x; acc[1] += a.y + b.y;
        }
    }
    if (j < s1) {
        int sA = g_src_sorted[j];
        const float* pA = Yb + (size_t)sA * ldy;
        if (V == 4) {
            float4 a = *(const float4*)pA;
            acc[0] += a.x; acc[1] += a.y; acc[2] += a.z; acc[3] += a.w;
        } else {
            float2 a = *(const float2*)pA;
            acc[0] += a.x; acc[1] += a.y;
        }
    }
    int deg = s1 - s0;
    float inv = 1.f / (float)(deg > 1 ? deg : 1);
    float o[V];
#pragma unroll
    for (int v = 0; v < V; v++) {
        float r = Y[(size_t)gw * ldy + rcol + col + v];
        float b = bias[col + v];
        o[v] = fmaxf(acc[v] * inv + r + b, 0.f);
    }
    if (V == 4)
        *(float4*)&Out[(size_t)gw * ldo + ocol + col] =
            make_float4(o[0], o[1], o[2], o[3]);
    else
        *(float2*)&Out[(size_t)gw * ldo + ocol + col] =
            make_float2(o[0], o[1]);
}

// ------------------------------- launcher ----------------------------------
extern "C" void kernel_launch(void* const* d_in, const int* in_sizes, int n_in,
                              void* d_out, int out_size)
{
    const float* x   = (const float*)d_in[0];
    const void*  eix = d_in[1];
    const float* Wp  = (const float*)d_in[2];
    const float* bp  = (const float*)d_in[3];
    const float* Wl1 = (const float*)d_in[4];
    const float* bl1 = (const float*)d_in[5];
    const float* Wr1 = (const float*)d_in[6];
    const float* Wl2 = (const float*)d_in[7];
    const float* bl2 = (const float*)d_in[8];
    const float* Wr2 = (const float*)d_in[9];
    const float* Wl3 = (const float*)d_in[10];
    const float* bl3 = (const float*)d_in[11];
    const float* Wr3 = (const float*)d_in[12];

    int N = in_sizes[0] / 64;
    int E = in_sizes[1] / 2;
    float* out = (float*)d_out;

    float *dF, *dY, *dW;
    cudaGetSymbolAddress((void**)&dF, g_F);
    cudaGetSymbolAddress((void**)&dY, g_Y);
    cudaGetSymbolAddress((void**)&dW, g_Wcat);

    // ---- CSR build ----
    detect_kernel<<<1, 32>>>((const unsigned int*)eix);
    zero_cnt<<<(N + 255) / 256, 256>>>(N);
    hist_kernel<<<(E + 255) / 256, 256>>>(eix, E);
    scan_kernel<<<1, 1024>>>(N);
    scatter_kernel<<<(E + 255) / 256, 256>>>(eix, E);

    int mg = (N + 63) / 64;

    // ---- layer 1 ----
    // x_p = relu(x @ Wp + bp)  -> F[:,0:64]
    sgemm_kernel<<<dim3(mg, 1), 256>>>(x, 64, Wp, bp, dF, 256, 0,
                                       N, 64, 64, 1);
    // [y1 | r1] = x @ [Wl1 | Wr1] -> Y[:,0:128]
    pack2_kernel<<<(64 * 64 + 255) / 256, 256>>>(Wl1, Wr1, 64, 64);
    sgemm_kernel<<<dim3(mg, 2), 256>>>(x, 64, dW, nullptr, dY, 256, 0,
                                       N, 128, 64, 0);
    // h1 = relu(mean(y1) + bl1 + r1) -> F[:,64:128]
    agg_kernel<2><<<(N + 7) / 8, 256>>>(dY, 256, 0, 64, bl1, dF, 256, 64, N);

    // ---- layer 2 ----  in2 = F[:,0:128]
    pack2_kernel<<<(128 * 128 + 255) / 256, 256>>>(Wl2, Wr2, 128, 128);
    sgemm_kernel<<<dim3(mg, 4), 256>>>(dF, 256, dW, nullptr, dY, 256, 0,
                                       N, 256, 128, 0);
    agg_kernel<4><<<(N + 7) / 8, 256>>>(dY, 256, 0, 128, bl2, dF, 256, 128, N);

    // ---- layer 3 ----  in3 = F[:,0:256]
    pack2_kernel<<<(256 * 128 + 255) / 256, 256>>>(Wl3, Wr3, 256, 128);
    sgemm_kernel<<<dim3(mg, 4), 256>>>(dF, 256, dW, nullptr, dY, 256, 0,
                                       N, 256, 256, 0);
    agg_kernel<4><<<(N + 7) / 8, 256>>>(dY, 256, 0, 128, bl3, out, 128, 0, N);
}

// round 2
// speedup vs baseline: 1.2241x; 1.2241x over previous
#include <cuda_runtime.h>
#include <cstdint>

// ---------------------------------------------------------------------------
// DenseGCN (3-layer GraphSAGE, mean aggr) on GB300.
//   - matmul BEFORE mean-aggregation (linearity) => layer3 gather 256->128.
//   - CSR build (histogram + multi-block scan + scatter), gather-side agg.
//   - fused concatenated GEMMs x@[Wl|Wr]; 128x128-tile fp32 SGEMM.
// ---------------------------------------------------------------------------

#define NMAX 50176
#define EMAX 1000448
#define SCAN_B 1024

__device__ __align__(16) float g_F[(size_t)NMAX * 256];
__device__ __align__(16) float g_Y[(size_t)NMAX * 256];
__device__ __align__(16) float g_Wcat[256 * 256];
__device__ int g_row_off[NMAX + 1];
__device__ int g_cnt[NMAX];
__device__ int g_bsum[64];
__device__ int g_src_sorted[EMAX];
__device__ int g_is64;

// --------------------------- edge dtype detection --------------------------
__global__ void detect_kernel(const unsigned int* e) {
    if (threadIdx.x == 0) {
        int is64 = 1;
        for (int i = 0; i < 8; i++)
            if (e[2 * i + 1] != 0u) is64 = 0;  // high word of int64 elems
        g_is64 = is64;
    }
}

__global__ void zero_cnt(int n) {
    int i = blockIdx.x * blockDim.x + threadIdx.x;
    if (i < n) g_cnt[i] = 0;
}

__global__ void hist_kernel(const void* e, int E) {
    int i = blockIdx.x * blockDim.x + threadIdx.x;
    if (i >= E) return;
    int dst;
    if (g_is64) dst = (int)((const long long*)e)[(size_t)E + i];
    else        dst = ((const int*)e)[E + i];
    atomicAdd(&g_cnt[dst], 1);
}

// ------------------------- multi-block exclusive scan ----------------------
// pass 1: per-block scan of g_cnt -> partial exclusive in g_row_off,
//         block totals -> g_bsum
__global__ void __launch_bounds__(SCAN_B) scan_blocks(int n) {
    __shared__ int wsum[32];
    int tid = threadIdx.x;
    int lane = tid & 31, wid = tid >> 5;
    int i = blockIdx.x * SCAN_B + tid;
    int v = (i < n) ? g_cnt[i] : 0;
    int incl = v;
#pragma unroll
    for (int off = 1; off < 32; off <<= 1) {
        int t = __shfl_up_sync(0xffffffffu, incl, off);
        if (lane >= off) incl += t;
    }
    if (lane == 31) wsum[wid] = incl;
    __syncthreads();
    if (wid == 0) {
        int w = wsum[lane];
#pragma unroll
        for (int off = 1; off < 32; off <<= 1) {
            int t = __shfl_up_sync(0xffffffffu, w, off);
            if (lane >= off) w += t;
        }
        wsum[lane] = w;
    }
    __syncthreads();
    int add = (wid > 0) ? wsum[wid - 1] : 0;
    int excl = add + incl - v;
    if (i < n) g_row_off[i] = excl;
    if (tid == SCAN_B - 1) g_bsum[blockIdx.x] = add + incl;  // block total
}

// pass 2: tiny exclusive scan of block sums (<=64 entries) by one thread
__global__ void scan_bsum(int nb) {
    if (threadIdx.x == 0) {
        int run = 0;
        for (int b = 0; b < nb; b++) {
            int t = g_bsum[b];
            g_bsum[b] = run;
            run += t;
        }
    }
}

// pass 3: add block offsets, finalize row_off and cursor
__global__ void __launch_bounds__(SCAN_B) scan_add(int n, int E) {
    int i = blockIdx.x * SCAN_B + threadIdx.x;
    if (i < n) {
        int v = g_row_off[i] + g_bsum[blockIdx.x];
        g_row_off[i] = v;
        g_cnt[i] = v;   // cursor for scatter
    }
    if (blockIdx.x == 0 && threadIdx.x == 0) g_row_off[n] = E;
}

__global__ void scatter_kernel(const void* e, int E) {
    int i = blockIdx.x * blockDim.x + threadIdx.x;
    if (i >= E) return;
    int src, dst;
    if (g_is64) {
        src = (int)((const long long*)e)[i];
        dst = (int)((const long long*)e)[(size_t)E + i];
    } else {
        src = ((const int*)e)[i];
        dst = ((const int*)e)[E + i];
    }
    int pos = atomicAdd(&g_cnt[dst], 1);
    g_src_sorted[pos] = src;
}

// pack [Wl | Wr] -> g_Wcat  ([K, 2*Fo] row-major)
__global__ void pack2_kernel(const float* __restrict__ Wl,
                             const float* __restrict__ Wr, int K, int Fo) {
    int i = blockIdx.x * blockDim.x + threadIdx.x;
    if (i >= K * Fo) return;
    int k = i / Fo, n = i % Fo;
    g_Wcat[k * (2 * Fo) + n]      = Wl[i];
    g_Wcat[k * (2 * Fo) + Fo + n] = Wr[i];
}

// ---------------------- SGEMM 128x128 tile, 8x8 micro ----------------------
// C[M,N](+bias,+relu) = A[M,K] @ B[K,N]. N must be multiple of 128.
// Fragment layout: rows {ty*4+i, 64+ty*4+i}, cols {tx*4+j, 64+tx*4+j}.
__global__ void __launch_bounds__(256) sgemm128_kernel(
    const float* __restrict__ A, int lda,
    const float* __restrict__ B,
    const float* __restrict__ bias,
    float* __restrict__ C, int ldc, int coff,
    int M, int N, int K, int do_relu)
{
    __shared__ float As[16][132];
    __shared__ float Bs[16][132];
    int tid = threadIdx.x;
    int tx = tid & 15, ty = tid >> 4;
    int m0 = blockIdx.x << 7, n0 = blockIdx.y << 7;

    float acc[8][8];
#pragma unroll
    for (int i = 0; i < 8; i++)
#pragma unroll
        for (int j = 0; j < 8; j++) acc[i][j] = 0.f;

    int arow = tid >> 1;            // 0..127
    int acol = (tid & 1) << 3;      // 0 or 8
    int brow = tid >> 4;            // 0..15
    int bcol = (tid & 15) << 3;     // 0..120
    int am = m0 + arow;

    for (int k0 = 0; k0 < K; k0 += 16) {
        float4 a0 = make_float4(0.f, 0.f, 0.f, 0.f), a1 = a0;
        if (am < M) {
            a0 = *(const float4*)&A[(size_t)am * lda + k0 + acol];
            a1 = *(const float4*)&A[(size_t)am * lda + k0 + acol + 4];
        }
        As[acol + 0][arow] = a0.x; As[acol + 1][arow] = a0.y;
        As[acol + 2][arow] = a0.z; As[acol + 3][arow] = a0.w;
        As[acol + 4][arow] = a1.x; As[acol + 5][arow] = a1.y;
        As[acol + 6][arow] = a1.z; As[acol + 7][arow] = a1.w;
        const float* Bp = &B[(size_t)(k0 + brow) * N + n0 + bcol];
        *(float4*)&Bs[brow][bcol]     = *(const float4*)Bp;
        *(float4*)&Bs[brow][bcol + 4] = *(const float4*)(Bp + 4);
        __syncthreads();
#pragma unroll
        for (int k = 0; k < 16; k++) {
            float a[8], b[8];
            *(float4*)&a[0] = *(float4*)&As[k][ty << 2];
            *(float4*)&a[4] = *(float4*)&As[k][64 + (ty << 2)];
            *(float4*)&b[0] = *(float4*)&Bs[k][tx << 2];
            *(float4*)&b[4] = *(float4*)&Bs[k][64 + (tx << 2)];
#pragma unroll
            for (int i = 0; i < 8; i++)
#pragma unroll
                for (int j = 0; j < 8; j++)
                    acc[i][j] += a[i] * b[j];
        }
        __syncthreads();
    }

    float bb[8] = {0.f, 0.f, 0.f, 0.f, 0.f, 0.f, 0.f, 0.f};
    if (bias) {
        *(float4*)&bb[0] = *(const float4*)&bias[n0 + (tx << 2)];
        *(float4*)&bb[4] = *(const float4*)&bias[n0 + 64 + (tx << 2)];
    }
#pragma unroll
    for (int i = 0; i < 8; i++) {
        int m = m0 + ((i < 4) ? ((ty << 2) + i) : (64 + (ty << 2) + i - 4));
        if (m >= M) continue;
        float4 v0, v1;
        v0.x = acc[i][0] + bb[0]; v0.y = acc[i][1] + bb[1];
        v0.z = acc[i][2] + bb[2]; v0.w = acc[i][3] + bb[3];
        v1.x = acc[i][4] + bb[4]; v1.y = acc[i][5] + bb[5];
        v1.z = acc[i][6] + bb[6]; v1.w = acc[i][7] + bb[7];
        if (do_relu) {
            v0.x = fmaxf(v0.x, 0.f); v0.y = fmaxf(v0.y, 0.f);
            v0.z = fmaxf(v0.z, 0.f); v0.w = fmaxf(v0.w, 0.f);
            v1.x = fmaxf(v1.x, 0.f); v1.y = fmaxf(v1.y, 0.f);
            v1.z = fmaxf(v1.z, 0.f); v1.w = fmaxf(v1.w, 0.f);
        }
        float* Cp = &C[(size_t)m * ldc + coff + n0];
        *(float4*)&Cp[tx << 2]        = v0;
        *(float4*)&Cp[64 + (tx << 2)] = v1;
    }
}

// ------------------- small SGEMM (64x64 tile) for N=64 ---------------------
__global__ void __launch_bounds__(256) sgemm64_kernel(
    const float* __restrict__ A, int lda,
    const float* __restrict__ B,
    const float* __restrict__ bias,
    float* __restrict__ C, int ldc, int coff,
    int M, int N, int K, int do_relu)
{
    __shared__ float As[16][68];
    __shared__ float Bs[16][68];
    int tid = threadIdx.x;
    int tx = tid & 15, ty = tid >> 4;
    int m0 = blockIdx.x << 6, n0 = blockIdx.y << 6;
    float acc[4][4];
#pragma unroll
    for (int i = 0; i < 4; i++)
#pragma unroll
        for (int j = 0; j < 4; j++) acc[i][j] = 0.f;

    int ar = tid >> 2;
    int ac = (tid & 3) << 2;
    int br = tid >> 4;
    int bc = (tid & 15) << 2;
    int am = m0 + ar;

    for (int k0 = 0; k0 < K; k0 += 16) {
        float4 a4 = make_float4(0.f, 0.f, 0.f, 0.f);
        if (am < M) a4 = *(const float4*)&A[(size_t)am * lda + k0 + ac];
        As[ac + 0][ar] = a4.x; As[ac + 1][ar] = a4.y;
        As[ac + 2][ar] = a4.z; As[ac + 3][ar] = a4.w;
        *(float4*)&Bs[br][bc] = *(const float4*)&B[(size_t)(k0 + br) * N + n0 + bc];
        __syncthreads();
#pragma unroll
        for (int k = 0; k < 16; k++) {
            float4 a = *(float4*)&As[k][ty << 2];
            float4 b = *(float4*)&Bs[k][tx << 2];
            acc[0][0] += a.x * b.x; acc[0][1] += a.x * b.y;
            acc[0][2] += a.x * b.z; acc[0][3] += a.x * b.w;
            acc[1][0] += a.y * b.x; acc[1][1] += a.y * b.y;
            acc[1][2] += a.y * b.z; acc[1][3] += a.y * b.w;
            acc[2][0] += a.z * b.x; acc[2][1] += a.z * b.y;
            acc[2][2] += a.z * b.z; acc[2][3] += a.z * b.w;
            acc[3][0] += a.w * b.x; acc[3][1] += a.w * b.y;
            acc[3][2] += a.w * b.z; acc[3][3] += a.w * b.w;
        }
        __syncthreads();
    }
    float4 bb = make_float4(0.f, 0.f, 0.f, 0.f);
    if (bias) bb = *(const float4*)&bias[n0 + (tx << 2)];
#pragma unroll
    for (int i = 0; i < 4; i++) {
        int m = m0 + (ty << 2) + i;
        if (m < M) {
            float4 v;
            v.x = acc[i][0] + bb.x; v.y = acc[i][1] + bb.y;
            v.z = acc[i][2] + bb.z; v.w = acc[i][3] + bb.w;
            if (do_relu) {
                v.x = fmaxf(v.x, 0.f); v.y = fmaxf(v.y, 0.f);
                v.z = fmaxf(v.z, 0.f); v.w = fmaxf(v.w, 0.f);
            }
            *(float4*)&C[(size_t)m * ldc + coff + n0 + (tx << 2)] = v;
        }
    }
}

// ------------------------------ aggregation --------------------------------
template <int V>
__global__ void agg_kernel(const float* __restrict__ Y, int ldy, int ycol,
                           int rcol, const float* __restrict__ bias,
                           float* __restrict__ Out, int ldo, int ocol, int Nn)
{
    int gw = (blockIdx.x * blockDim.x + threadIdx.x) >> 5;
    int lane = threadIdx.x & 31;
    if (gw >= Nn) return;
    int s0 = g_row_off[gw], s1 = g_row_off[gw + 1];
    int col = lane * V;
    float acc[V];
#pragma unroll
    for (int v = 0; v < V; v++) acc[v] = 0.f;
    const float* Yb = Y + ycol + col;

    int j = s0;
    for (; j + 1 < s1; j += 2) {
        int sA = g_src_sorted[j];
        int sB = g_src_sorted[j + 1];
        const float* pA = Yb + (size_t)sA * ldy;
        const float* pB = Yb + (size_t)sB * ldy;
        if (V == 4) {
            float4 a = *(const float4*)pA;
            float4 b = *(const float4*)pB;
            acc[0] += a.x + b.x; acc[1] += a.y + b.y;
            acc[2] += a.z + b.z; acc[3] += a.w + b.w;
        } else {
            float2 a = *(const float2*)pA;
            float2 b = *(const float2*)pB;
            acc[0] += a.x + b.x; acc[1] += a.y + b.y;
        }
    }
    if (j < s1) {
        int sA = g_src_sorted[j];
        const float* pA = Yb + (size_t)sA * ldy;
        if (V == 4) {
            float4 a = *(const float4*)pA;
            acc[0] += a.x; acc[1] += a.y; acc[2] += a.z; acc[3] += a.w;
        } else {
            float2 a = *(const float2*)pA;
            acc[0] += a.x; acc[1] += a.y;
        }
    }
    int deg = s1 - s0;
    float inv = 1.f / (float)(deg > 1 ? deg : 1);
    float o[V];
#pragma unroll
    for (int v = 0; v < V; v++) {
        float r = Y[(size_t)gw * ldy + rcol + col + v];
        float b = bias[col + v];
        o[v] = fmaxf(acc[v] * inv + r + b, 0.f);
    }
    if (V == 4)
        *(float4*)&Out[(size_t)gw * ldo + ocol + col] =
            make_float4(o[0], o[1], o[2], o[3]);
    else
        *(float2*)&Out[(size_t)gw * ldo + ocol + col] =
            make_float2(o[0], o[1]);
}

// ------------------------------- launcher ----------------------------------
extern "C" void kernel_launch(void* const* d_in, const int* in_sizes, int n_in,
                              void* d_out, int out_size)
{
    const float* x   = (const float*)d_in[0];
    const void*  eix = d_in[1];
    const float* Wp  = (const float*)d_in[2];
    const float* bp  = (const float*)d_in[3];
    const float* Wl1 = (const float*)d_in[4];
    const float* bl1 = (const float*)d_in[5];
    const float* Wr1 = (const float*)d_in[6];
    const float* Wl2 = (const float*)d_in[7];
    const float* bl2 = (const float*)d_in[8];
    const float* Wr2 = (const float*)d_in[9];
    const float* Wl3 = (const float*)d_in[10];
    const float* bl3 = (const float*)d_in[11];
    const float* Wr3 = (const float*)d_in[12];

    int N = in_sizes[0] / 64;
    int E = in_sizes[1] / 2;
    float* out = (float*)d_out;

    float *dF, *dY, *dW;
    cudaGetSymbolAddress((void**)&dF, g_F);
    cudaGetSymbolAddress((void**)&dY, g_Y);
    cudaGetSymbolAddress((void**)&dW, g_Wcat);

    int nb = (N + SCAN_B - 1) / SCAN_B;

    // ---- CSR build ----
    detect_kernel<<<1, 32>>>((const unsigned int*)eix);
    zero_cnt<<<(N + 255) / 256, 256>>>(N);
    hist_kernel<<<(E + 255) / 256, 256>>>(eix, E);
    scan_blocks<<<nb, SCAN_B>>>(N);
    scan_bsum<<<1, 32>>>(nb);
    scan_add<<<nb, SCAN_B>>>(N, E);
    scatter_kernel<<<(E + 255) / 256, 256>>>(eix, E);

    int mg64  = (N + 63) / 64;
    int mg128 = (N + 127) / 128;

    // ---- layer 1 ----
    sgemm64_kernel<<<dim3(mg64, 1), 256>>>(x, 64, Wp, bp, dF, 256, 0,
                                           N, 64, 64, 1);
    pack2_kernel<<<(64 * 64 + 255) / 256, 256>>>(Wl1, Wr1, 64, 64);
    sgemm128_kernel<<<dim3(mg128, 1), 256>>>(x, 64, dW, nullptr, dY, 256, 0,
                                             N, 128, 64, 0);
    agg_kernel<2><<<(N + 7) / 8, 256>>>(dY, 256, 0, 64, bl1, dF, 256, 64, N);

    // ---- layer 2 ----  in2 = F[:,0:128]
    pack2_kernel<<<(128 * 128 + 255) / 256, 256>>>(Wl2, Wr2, 128, 128);
    sgemm128_kernel<<<dim3(mg128, 2), 256>>>(dF, 256, dW, nullptr, dY, 256, 0,
                                             N, 256, 128, 0);
    agg_kernel<4><<<(N + 7) / 8, 256>>>(dY, 256, 0, 128, bl2, dF, 256, 128, N);

    // ---- layer 3 ----  in3 = F[:,0:256]
    pack2_kernel<<<(256 * 128 + 255) / 256, 256>>>(Wl3, Wr3, 256, 128);
    sgemm128_kernel<<<dim3(mg128, 2), 256>>>(dF, 256, dW, nullptr, dY, 256, 0,
                                             N, 256, 256, 0);
    agg_kernel<4><<<(N + 7) / 8, 256>>>(dY, 256, 0, 128, bl3, out, 128, 0, N);
}

// round 3
// speedup vs baseline: 1.2572x; 1.0270x over previous
#include <cuda_runtime.h>
#include <cstdint>

// ---------------------------------------------------------------------------
// DenseGCN (3-layer GraphSAGE, mean aggr) on GB300.
//   - matmul BEFORE mean-aggregation (linearity) => layer3 gather 256->128.
//   - CSR build (histogram + multi-block scan + scatter), gather-side agg.
//   - fused concatenated GEMMs x@[Wl|Wr]; fp32 SGEMM with packed FFMA2
//     (PTX fma.rn.f32x2: 2 fp32 FMAs per issue slot, bit-exact).
// ---------------------------------------------------------------------------

#define NMAX 50176
#define EMAX 1000448
#define SCAN_B 1024

__device__ __align__(16) float g_F[(size_t)NMAX * 256];
__device__ __align__(16) float g_Y[(size_t)NMAX * 256];
__device__ __align__(16) float g_Wcat[256 * 256];
__device__ int g_row_off[NMAX + 1];
__device__ int g_cnt[NMAX];
__device__ int g_bsum[64];
__device__ int g_src_sorted[EMAX];
__device__ int g_is64;

// packed f32x2 helpers --------------------------------------------------------
__device__ __forceinline__ unsigned long long pack2(float lo, float hi) {
    unsigned long long r;
    asm("mov.b64 %0, {%1, %2};" : "=l"(r) : "f"(lo), "f"(hi));
    return r;
}
__device__ __forceinline__ void unpack2(unsigned long long v, float& lo, float& hi) {
    asm("mov.b64 {%0, %1}, %2;" : "=f"(lo), "=f"(hi) : "l"(v));
}
__device__ __forceinline__ void fma2(unsigned long long& d,
                                     unsigned long long a,
                                     unsigned long long b) {
    asm("fma.rn.f32x2 %0, %1, %2, %3;" : "=l"(d) : "l"(a), "l"(b), "l"(d));
}

// --------------------------- edge dtype detection --------------------------
__global__ void detect_kernel(const unsigned int* e) {
    if (threadIdx.x == 0) {
        int is64 = 1;
        for (int i = 0; i < 8; i++)
            if (e[2 * i + 1] != 0u) is64 = 0;  // high word of int64 elems
        g_is64 = is64;
    }
}

__global__ void zero_cnt(int n) {
    int i = blockIdx.x * blockDim.x + threadIdx.x;
    if (i < n) g_cnt[i] = 0;
}

__global__ void hist_kernel(const void* e, int E) {
    int i = blockIdx.x * blockDim.x + threadIdx.x;
    if (i >= E) return;
    int dst;
    if (g_is64) dst = (int)((const long long*)e)[(size_t)E + i];
    else        dst = ((const int*)e)[E + i];
    atomicAdd(&g_cnt[dst], 1);
}

// ------------------------- multi-block exclusive scan ----------------------
__global__ void __launch_bounds__(SCAN_B) scan_blocks(int n) {
    __shared__ int wsum[32];
    int tid = threadIdx.x;
    int lane = tid & 31, wid = tid >> 5;
    int i = blockIdx.x * SCAN_B + tid;
    int v = (i < n) ? g_cnt[i] : 0;
    int incl = v;
#pragma unroll
    for (int off = 1; off < 32; off <<= 1) {
        int t = __shfl_up_sync(0xffffffffu, incl, off);
        if (lane >= off) incl += t;
    }
    if (lane == 31) wsum[wid] = incl;
    __syncthreads();
    if (wid == 0) {
        int w = wsum[lane];
#pragma unroll
        for (int off = 1; off < 32; off <<= 1) {
            int t = __shfl_up_sync(0xffffffffu, w, off);
            if (lane >= off) w += t;
        }
        wsum[lane] = w;
    }
    __syncthreads();
    int add = (wid > 0) ? wsum[wid - 1] : 0;
    int excl = add + incl - v;
    if (i < n) g_row_off[i] = excl;
    if (tid == SCAN_B - 1) g_bsum[blockIdx.x] = add + incl;
}

__global__ void scan_bsum(int nb) {
    if (threadIdx.x == 0) {
        int run = 0;
        for (int b = 0; b < nb; b++) {
            int t = g_bsum[b];
            g_bsum[b] = run;
            run += t;
        }
    }
}

__global__ void __launch_bounds__(SCAN_B) scan_add(int n, int E) {
    int i = blockIdx.x * SCAN_B + threadIdx.x;
    if (i < n) {
        int v = g_row_off[i] + g_bsum[blockIdx.x];
        g_row_off[i] = v;
        g_cnt[i] = v;   // cursor for scatter
    }
    if (blockIdx.x == 0 && threadIdx.x == 0) g_row_off[n] = E;
}

__global__ void scatter_kernel(const void* e, int E) {
    int i = blockIdx.x * blockDim.x + threadIdx.x;
    if (i >= E) return;
    int src, dst;
    if (g_is64) {
        src = (int)((const long long*)e)[i];
        dst = (int)((const long long*)e)[(size_t)E + i];
    } else {
        src = ((const int*)e)[i];
        dst = ((const int*)e)[E + i];
    }
    int pos = atomicAdd(&g_cnt[dst], 1);
    g_src_sorted[pos] = src;
}

// pack [Wl | Wr] -> g_Wcat  ([K, 2*Fo] row-major)
__global__ void pack2_kernel(const float* __restrict__ Wl,
                             const float* __restrict__ Wr, int K, int Fo) {
    int i = blockIdx.x * blockDim.x + threadIdx.x;
    if (i >= K * Fo) return;
    int k = i / Fo, n = i % Fo;
    g_Wcat[k * (2 * Fo) + n]      = Wl[i];
    g_Wcat[k * (2 * Fo) + Fo + n] = Wr[i];
}

// ---------------- SGEMM 128x128 tile, 8x8 micro, FFMA2 ---------------------
__global__ void __launch_bounds__(256) sgemm128_kernel(
    const float* __restrict__ A, int lda,
    const float* __restrict__ B,
    const float* __restrict__ bias,
    float* __restrict__ C, int ldc, int coff,
    int M, int N, int K, int do_relu)
{
    __shared__ float As[16][132];
    __shared__ float Bs[16][132];
    int tid = threadIdx.x;
    int tx = tid & 15, ty = tid >> 4;
    int m0 = blockIdx.x << 7, n0 = blockIdx.y << 7;

    unsigned long long acc[8][4];
#pragma unroll
    for (int i = 0; i < 8; i++)
#pragma unroll
        for (int j = 0; j < 4; j++) acc[i][j] = 0ull;

    int arow = tid >> 1;            // 0..127
    int acol = (tid & 1) << 3;      // 0 or 8
    int brow = tid >> 4;            // 0..15
    int bcol = (tid & 15) << 3;     // 0..120
    int am = m0 + arow;

    for (int k0 = 0; k0 < K; k0 += 16) {
        float4 a0 = make_float4(0.f, 0.f, 0.f, 0.f), a1 = a0;
        if (am < M) {
            a0 = *(const float4*)&A[(size_t)am * lda + k0 + acol];
            a1 = *(const float4*)&A[(size_t)am * lda + k0 + acol + 4];
        }
        As[acol + 0][arow] = a0.x; As[acol + 1][arow] = a0.y;
        As[acol + 2][arow] = a0.z; As[acol + 3][arow] = a0.w;
        As[acol + 4][arow] = a1.x; As[acol + 5][arow] = a1.y;
        As[acol + 6][arow] = a1.z; As[acol + 7][arow] = a1.w;
        const float* Bp = &B[(size_t)(k0 + brow) * N + n0 + bcol];
        *(float4*)&Bs[brow][bcol]     = *(const float4*)Bp;
        *(float4*)&Bs[brow][bcol + 4] = *(const float4*)(Bp + 4);
        __syncthreads();
#pragma unroll
        for (int k = 0; k < 16; k++) {
            float a[8];
            *(float4*)&a[0] = *(float4*)&As[k][ty << 2];
            *(float4*)&a[4] = *(float4*)&As[k][64 + (ty << 2)];
            float b[8];
            *(float4*)&b[0] = *(float4*)&Bs[k][tx << 2];
            *(float4*)&b[4] = *(float4*)&Bs[k][64 + (tx << 2)];
            unsigned long long bv[4], av[8];
            bv[0] = pack2(b[0], b[1]); bv[1] = pack2(b[2], b[3]);
            bv[2] = pack2(b[4], b[5]); bv[3] = pack2(b[6], b[7]);
#pragma unroll
            for (int i = 0; i < 8; i++) av[i] = pack2(a[i], a[i]);
#pragma unroll
            for (int i = 0; i < 8; i++) {
                fma2(acc[i][0], av[i], bv[0]);
                fma2(acc[i][1], av[i], bv[1]);
                fma2(acc[i][2], av[i], bv[2]);
                fma2(acc[i][3], av[i], bv[3]);
            }
        }
        __syncthreads();
    }

    float bb[8] = {0.f, 0.f, 0.f, 0.f, 0.f, 0.f, 0.f, 0.f};
    if (bias) {
        *(float4*)&bb[0] = *(const float4*)&bias[n0 + (tx << 2)];
        *(float4*)&bb[4] = *(const float4*)&bias[n0 + 64 + (tx << 2)];
    }
#pragma unroll
    for (int i = 0; i < 8; i++) {
        int m = m0 + ((i < 4) ? ((ty << 2) + i) : (64 + (ty << 2) + i - 4));
        if (m >= M) continue;
        float c[8];
        unpack2(acc[i][0], c[0], c[1]); unpack2(acc[i][1], c[2], c[3]);
        unpack2(acc[i][2], c[4], c[5]); unpack2(acc[i][3], c[6], c[7]);
        float4 v0, v1;
        v0.x = c[0] + bb[0]; v0.y = c[1] + bb[1];
        v0.z = c[2] + bb[2]; v0.w = c[3] + bb[3];
        v1.x = c[4] + bb[4]; v1.y = c[5] + bb[5];
        v1.z = c[6] + bb[6]; v1.w = c[7] + bb[7];
        if (do_relu) {
            v0.x = fmaxf(v0.x, 0.f); v0.y = fmaxf(v0.y, 0.f);
            v0.z = fmaxf(v0.z, 0.f); v0.w = fmaxf(v0.w, 0.f);
            v1.x = fmaxf(v1.x, 0.f); v1.y = fmaxf(v1.y, 0.f);
            v1.z = fmaxf(v1.z, 0.f); v1.w = fmaxf(v1.w, 0.f);
        }
        float* Cp = &C[(size_t)m * ldc + coff + n0];
        *(float4*)&Cp[tx << 2]        = v0;
        *(float4*)&Cp[64 + (tx << 2)] = v1;
    }
}

// ------------- small SGEMM (64x64 tile, FFMA2) for N=64 --------------------
__global__ void __launch_bounds__(256) sgemm64_kernel(
    const float* __restrict__ A, int lda,
    const float* __restrict__ B,
    const float* __restrict__ bias,
    float* __restrict__ C, int ldc, int coff,
    int M, int N, int K, int do_relu)
{
    __shared__ float As[16][68];
    __shared__ float Bs[16][68];
    int tid = threadIdx.x;
    int tx = tid & 15, ty = tid >> 4;
    int m0 = blockIdx.x << 6, n0 = blockIdx.y << 6;
    unsigned long long acc[4][2];
#pragma unroll
    for (int i = 0; i < 4; i++) { acc[i][0] = 0ull; acc[i][1] = 0ull; }

    int ar = tid >> 2;
    int ac = (tid & 3) << 2;
    int br = tid >> 4;
    int bc = (tid & 15) << 2;
    int am = m0 + ar;

    for (int k0 = 0; k0 < K; k0 += 16) {
        float4 a4 = make_float4(0.f, 0.f, 0.f, 0.f);
        if (am < M) a4 = *(const float4*)&A[(size_t)am * lda + k0 + ac];
        As[ac + 0][ar] = a4.x; As[ac + 1][ar] = a4.y;
        As[ac + 2][ar] = a4.z; As[ac + 3][ar] = a4.w;
        *(float4*)&Bs[br][bc] = *(const float4*)&B[(size_t)(k0 + br) * N + n0 + bc];
        __syncthreads();
#pragma unroll
        for (int k = 0; k < 16; k++) {
            float4 a = *(float4*)&As[k][ty << 2];
            float4 b = *(float4*)&Bs[k][tx << 2];
            unsigned long long bv0 = pack2(b.x, b.y), bv1 = pack2(b.z, b.w);
            unsigned long long av;
            av = pack2(a.x, a.x); fma2(acc[0][0], av, bv0); fma2(acc[0][1], av, bv1);
            av = pack2(a.y, a.y); fma2(acc[1][0], av, bv0); fma2(acc[1][1], av, bv1);
            av = pack2(a.z, a.z); fma2(acc[2][0], av, bv0); fma2(acc[2][1], av, bv1);
            av = pack2(a.w, a.w); fma2(acc[3][0], av, bv0); fma2(acc[3][1], av, bv1);
        }
        __syncthreads();
    }
    float4 bb = make_float4(0.f, 0.f, 0.f, 0.f);
    if (bias) bb = *(const float4*)&bias[n0 + (tx << 2)];
#pragma unroll
    for (int i = 0; i < 4; i++) {
        int m = m0 + (ty << 2) + i;
        if (m < M) {
            float c0, c1, c2, c3;
            unpack2(acc[i][0], c0, c1); unpack2(acc[i][1], c2, c3);
            float4 v;
            v.x = c0 + bb.x; v.y = c1 + bb.y;
            v.z = c2 + bb.z; v.w = c3 + bb.w;
            if (do_relu) {
                v.x = fmaxf(v.x, 0.f); v.y = fmaxf(v.y, 0.f);
                v.z = fmaxf(v.z, 0.f); v.w = fmaxf(v.w, 0.f);
            }
            *(float4*)&C[(size_t)m * ldc + coff + n0 + (tx << 2)] = v;
        }
    }
}

// ------------------------------ aggregation --------------------------------
template <int V>
__global__ void agg_kernel(const float* __restrict__ Y, int ldy, int ycol,
                           int rcol, const float* __restrict__ bias,
                           float* __restrict__ Out, int ldo, int ocol, int Nn)
{
    int gw = (blockIdx.x * blockDim.x + threadIdx.x) >> 5;
    int lane = threadIdx.x & 31;
    if (gw >= Nn) return;
    int s0 = g_row_off[gw], s1 = g_row_off[gw + 1];
    int col = lane * V;
    float acc[V];
#pragma unroll
    for (int v = 0; v < V; v++) acc[v] = 0.f;
    const float* Yb = Y + ycol + col;

    int j = s0;
    for (; j + 1 < s1; j += 2) {
        int sA = g_src_sorted[j];
        int sB = g_src_sorted[j + 1];
        const float* pA = Yb + (size_t)sA * ldy;
        const float* pB = Yb + (size_t)sB * ldy;
        if (V == 4) {
            float4 a = *(const float4*)pA;
            float4 b = *(const float4*)pB;
            acc[0] += a.x + b.x; acc[1] += a.y + b.y;
            acc[2] += a.z + b.z; acc[3] += a.w + b.w;
        } else {
            float2 a = *(const float2*)pA;
            float2 b = *(const float2*)pB;
            acc[0] += a.x + b.x; acc[1] += a.y + b.y;
        }
    }
    if (j < s1) {
        int sA = g_src_sorted[j];
        const float* pA = Yb + (size_t)sA * ldy;
        if (V == 4) {
            float4 a = *(const float4*)pA;
            acc[0] += a.x; acc[1] += a.y; acc[2] += a.z; acc[3] += a.w;
        } else {
            float2 a = *(const float2*)pA;
            acc[0] += a.x; acc[1] += a.y;
        }
    }
    int deg = s1 - s0;
    float inv = 1.f / (float)(deg > 1 ? deg : 1);
    float o[V];
#pragma unroll
    for (int v = 0; v < V; v++) {
        float r = Y[(size_t)gw * ldy + rcol + col + v];
        float b = bias[col + v];
        o[v] = fmaxf(acc[v] * inv + r + b, 0.f);
    }
    if (V == 4)
        *(float4*)&Out[(size_t)gw * ldo + ocol + col] =
            make_float4(o[0], o[1], o[2], o[3]);
    else
        *(float2*)&Out[(size_t)gw * ldo + ocol + col] =
            make_float2(o[0], o[1]);
}

// ------------------------------- launcher ----------------------------------
extern "C" void kernel_launch(void* const* d_in, const int* in_sizes, int n_in,
                              void* d_out, int out_size)
{
    const float* x   = (const float*)d_in[0];
    const void*  eix = d_in[1];
    const float* Wp  = (const float*)d_in[2];
    const float* bp  = (const float*)d_in[3];
    const float* Wl1 = (const float*)d_in[4];
    const float* bl1 = (const float*)d_in[5];
    const float* Wr1 = (const float*)d_in[6];
    const float* Wl2 = (const float*)d_in[7];
    const float* bl2 = (const float*)d_in[8];
    const float* Wr2 = (const float*)d_in[9];
    const float* Wl3 = (const float*)d_in[10];
    const float* bl3 = (const float*)d_in[11];
    const float* Wr3 = (const float*)d_in[12];

    int N = in_sizes[0] / 64;
    int E = in_sizes[1] / 2;
    float* out = (float*)d_out;

    float *dF, *dY, *dW;
    cudaGetSymbolAddress((void**)&dF, g_F);
    cudaGetSymbolAddress((void**)&dY, g_Y);
    cudaGetSymbolAddress((void**)&dW, g_Wcat);

    int nb = (N + SCAN_B - 1) / SCAN_B;

    // ---- CSR build ----
    detect_kernel<<<1, 32>>>((const unsigned int*)eix);
    zero_cnt<<<(N + 255) / 256, 256>>>(N);
    hist_kernel<<<(E + 255) / 256, 256>>>(eix, E);
    scan_blocks<<<nb, SCAN_B>>>(N);
    scan_bsum<<<1, 32>>>(nb);
    scan_add<<<nb, SCAN_B>>>(N, E);
    scatter_kernel<<<(E + 255) / 256, 256>>>(eix, E);

    int mg64  = (N + 63) / 64;
    int mg128 = (N + 127) / 128;

    // ---- layer 1 ----
    sgemm64_kernel<<<dim3(mg64, 1), 256>>>(x, 64, Wp, bp, dF, 256, 0,
                                           N, 64, 64, 1);
    pack2_kernel<<<(64 * 64 + 255) / 256, 256>>>(Wl1, Wr1, 64, 64);
    sgemm128_kernel<<<dim3(mg128, 1), 256>>>(x, 64, dW, nullptr, dY, 256, 0,
                                             N, 128, 64, 0);
    agg_kernel<2><<<(N + 7) / 8, 256>>>(dY, 256, 0, 64, bl1, dF, 256, 64, N);

    // ---- layer 2 ----  in2 = F[:,0:128]
    pack2_kernel<<<(128 * 128 + 255) / 256, 256>>>(Wl2, Wr2, 128, 128);
    sgemm128_kernel<<<dim3(mg128, 2), 256>>>(dF, 256, dW, nullptr, dY, 256, 0,
                                             N, 256, 128, 0);
    agg_kernel<4><<<(N + 7) / 8, 256>>>(dY, 256, 0, 128, bl2, dF, 256, 128, N);

    // ---- layer 3 ----  in3 = F[:,0:256]
    pack2_kernel<<<(256 * 128 + 255) / 256, 256>>>(Wl3, Wr3, 256, 128);
    sgemm128_kernel<<<dim3(mg128, 2), 256>>>(dF, 256, dW, nullptr, dY, 256, 0,
                                             N, 256, 256, 0);
    agg_kernel<4><<<(N + 7) / 8, 256>>>(dY, 256, 0, 128, bl3, out, 128, 0, N);
}

// round 4
// speedup vs baseline: 1.4245x; 1.1331x over previous
#include <cuda_runtime.h>
#include <cuda_bf16.h>
#include <cstdint>

// ---------------------------------------------------------------------------
// DenseGCN (3-layer GraphSAGE, mean aggr) on GB300.
//   - matmul BEFORE mean-aggregation (linearity).
//   - CSR build (histogram + multi-block scan + scatter), gather-side agg.
//   - GEMMs on tensor cores: bf16 mma.sync.m16n8k16 with 3-term split
//     (A=Ah+Al, W=Wh+Wl; acc += Ah*Wh + Al*Wh + Ah*Wl), err ~1e-5.
// ---------------------------------------------------------------------------

#define NMAX 50176
#define EMAX 1000448
#define SCAN_B 1024

__device__ __align__(16) float g_F[(size_t)NMAX * 256];
__device__ __align__(16) float g_Y[(size_t)NMAX * 256];
__device__ __align__(16) __nv_bfloat16 g_Wh[110592];
__device__ __align__(16) __nv_bfloat16 g_Wlo[110592];
__device__ int g_row_off[NMAX + 1];
__device__ int g_cnt[NMAX];
__device__ int g_bsum[64];
__device__ int g_src_sorted[EMAX];
__device__ int g_is64;

// weight regions in g_Wh/g_Wlo ([N][K] row-major, K contiguous)
#define WOFF_P 0
#define WOFF_1 4096
#define WOFF_2 12288
#define WOFF_3 45056

// --------------------------- edge dtype detection --------------------------
__global__ void detect_kernel(const unsigned int* e) {
    if (threadIdx.x == 0) {
        int is64 = 1;
        for (int i = 0; i < 8; i++)
            if (e[2 * i + 1] != 0u) is64 = 0;
        g_is64 = is64;
    }
}

__global__ void zero_cnt(int n) {
    int i = blockIdx.x * blockDim.x + threadIdx.x;
    if (i < n) g_cnt[i] = 0;
}

__global__ void hist_kernel(const void* e, int E) {
    int i = blockIdx.x * blockDim.x + threadIdx.x;
    if (i >= E) return;
    int dst;
    if (g_is64) dst = (int)((const long long*)e)[(size_t)E + i];
    else        dst = ((const int*)e)[E + i];
    atomicAdd(&g_cnt[dst], 1);
}

// ------------------------- multi-block exclusive scan ----------------------
__global__ void __launch_bounds__(SCAN_B) scan_blocks(int n) {
    __shared__ int wsum[32];
    int tid = threadIdx.x;
    int lane = tid & 31, wid = tid >> 5;
    int i = blockIdx.x * SCAN_B + tid;
    int v = (i < n) ? g_cnt[i] : 0;
    int incl = v;
#pragma unroll
    for (int off = 1; off < 32; off <<= 1) {
        int t = __shfl_up_sync(0xffffffffu, incl, off);
        if (lane >= off) incl += t;
    }
    if (lane == 31) wsum[wid] = incl;
    __syncthreads();
    if (wid == 0) {
        int w = wsum[lane];
#pragma unroll
        for (int off = 1; off < 32; off <<= 1) {
            int t = __shfl_up_sync(0xffffffffu, w, off);
            if (lane >= off) w += t;
        }
        wsum[lane] = w;
    }
    __syncthreads();
    int add = (wid > 0) ? wsum[wid - 1] : 0;
    int excl = add + incl - v;
    if (i < n) g_row_off[i] = excl;
    if (tid == SCAN_B - 1) g_bsum[blockIdx.x] = add + incl;
}

__global__ void scan_bsum(int nb) {
    if (threadIdx.x == 0) {
        int run = 0;
        for (int b = 0; b < nb; b++) {
            int t = g_bsum[b];
            g_bsum[b] = run;
            run += t;
        }
    }
}

__global__ void __launch_bounds__(SCAN_B) scan_add(int n, int E) {
    int i = blockIdx.x * SCAN_B + threadIdx.x;
    if (i < n) {
        int v = g_row_off[i] + g_bsum[blockIdx.x];
        g_row_off[i] = v;
        g_cnt[i] = v;
    }
    if (blockIdx.x == 0 && threadIdx.x == 0) g_row_off[n] = E;
}

__global__ void scatter_kernel(const void* e, int E) {
    int i = blockIdx.x * blockDim.x + threadIdx.x;
    if (i >= E) return;
    int src, dst;
    if (g_is64) {
        src = (int)((const long long*)e)[i];
        dst = (int)((const long long*)e)[(size_t)E + i];
    } else {
        src = ((const int*)e)[i];
        dst = ((const int*)e)[E + i];
    }
    int pos = atomicAdd(&g_cnt[dst], 1);
    g_src_sorted[pos] = src;
}

// ------------------- weight convert: fp32 [K,Fo]x2 -> bf16 hi/lo [N][K] ----
__global__ void cvt_w_kernel(const float* __restrict__ Wl,
                             const float* __restrict__ Wr,
                             int K, int Fo, int n_total, int woff) {
    int i = blockIdx.x * blockDim.x + threadIdx.x;
    if (i >= n_total * K) return;
    int n = i / K, k = i % K;
    float w = (n < Fo) ? Wl[k * Fo + n] : Wr[k * Fo + (n - Fo)];
    __nv_bfloat16 hi = __float2bfloat16_rn(w);
    float lo = w - __bfloat162float(hi);
    g_Wh[woff + n * K + k]  = hi;
    g_Wlo[woff + n * K + k] = __float2bfloat16_rn(lo);
}

// --------------------------- tensor-core GEMM ------------------------------
// C[M,N](+bias,+relu) = A[M,K](fp32) @ W[K,N] using bf16 hi/lo 3-term split.
// Wh/Wlo are [N][K] row-major bf16. Block tile 128x128, 8 warps (4m x 2n),
// warp tile 32x64 via m16n8k16 mma.sync. K multiple of 32.
__device__ __forceinline__ void mma16816(float* c, const unsigned* a,
                                         unsigned b0, unsigned b1) {
    asm volatile(
        "mma.sync.aligned.m16n8k16.row.col.f32.bf16.bf16.f32 "
        "{%0,%1,%2,%3}, {%4,%5,%6,%7}, {%8,%9}, {%0,%1,%2,%3};"
        : "+f"(c[0]), "+f"(c[1]), "+f"(c[2]), "+f"(c[3])
        : "r"(a[0]), "r"(a[1]), "r"(a[2]), "r"(a[3]), "r"(b0), "r"(b1));
}

__global__ void __launch_bounds__(256) gemm_bf16x3_kernel(
    const float* __restrict__ A, int lda,
    const __nv_bfloat16* __restrict__ Wh,
    const __nv_bfloat16* __restrict__ Wlo,
    const float* __restrict__ bias,
    float* __restrict__ C, int ldc, int coff,
    int M, int N, int K, int do_relu)
{
    __shared__ __nv_bfloat16 Ah[128][40];
    __shared__ __nv_bfloat16 Al[128][40];
    __shared__ __nv_bfloat16 Bh[128][40];
    __shared__ __nv_bfloat16 Bl[128][40];

    int tid = threadIdx.x;
    int lane = tid & 31, wid = tid >> 5;
    int wm = wid & 3, wn = wid >> 2;          // 4 m-warps x 2 n-warps
    int g = lane >> 2, t4 = lane & 3;
    int m0 = blockIdx.x << 7, n0 = blockIdx.y << 7;

    float acc[2][8][4];
#pragma unroll
    for (int mi = 0; mi < 2; mi++)
#pragma unroll
        for (int ni = 0; ni < 8; ni++)
#pragma unroll
            for (int q = 0; q < 4; q++) acc[mi][ni][q] = 0.f;

    int srow = tid >> 1;              // 0..127
    int skh  = (tid & 1) << 4;        // 0 or 16

    for (int k0 = 0; k0 < K; k0 += 32) {
        // ---- stage A (fp32 -> bf16 hi/lo) ----
        {
            float v[16];
            int m = m0 + srow;
            if (m < M) {
                const float* Ap = A + (size_t)m * lda + k0 + skh;
                *(float4*)&v[0]  = *(const float4*)(Ap + 0);
                *(float4*)&v[4]  = *(const float4*)(Ap + 4);
                *(float4*)&v[8]  = *(const float4*)(Ap + 8);
                *(float4*)&v[12] = *(const float4*)(Ap + 12);
            } else {
#pragma unroll
                for (int i = 0; i < 16; i++) v[i] = 0.f;
            }
#pragma unroll
            for (int i = 0; i < 16; i++) {
                __nv_bfloat16 hi = __float2bfloat16_rn(v[i]);
                Ah[srow][skh + i] = hi;
                Al[srow][skh + i] =
                    __float2bfloat16_rn(v[i] - __bfloat162float(hi));
            }
        }
        // ---- stage B (precomputed bf16, [N][K]) ----
        {
            int n = n0 + srow;
            if (n < N) {
                const __nv_bfloat16* ph = Wh + (size_t)n * K + k0 + skh;
                const __nv_bfloat16* pl = Wlo + (size_t)n * K + k0 + skh;
                *(uint2*)&Bh[srow][skh + 0] = *(const uint2*)(ph + 0);
                *(uint2*)&Bh[srow][skh + 4] = *(const uint2*)(ph + 4);
                *(uint2*)&Bh[srow][skh + 8] = *(const uint2*)(ph + 8);
                *(uint2*)&Bh[srow][skh + 12] = *(const uint2*)(ph + 12);
                *(uint2*)&Bl[srow][skh + 0] = *(const uint2*)(pl + 0);
                *(uint2*)&Bl[srow][skh + 4] = *(const uint2*)(pl + 4);
                *(uint2*)&Bl[srow][skh + 8] = *(const uint2*)(pl + 8);
                *(uint2*)&Bl[srow][skh + 12] = *(const uint2*)(pl + 12);
            } else {
                uint2 z = make_uint2(0u, 0u);
#pragma unroll
                for (int i = 0; i < 16; i += 4) {
                    *(uint2*)&Bh[srow][skh + i] = z;
                    *(uint2*)&Bl[srow][skh + i] = z;
                }
            }
        }
        __syncthreads();

#pragma unroll
        for (int ks = 0; ks < 32; ks += 16) {
            unsigned ah[2][4], al[2][4];
#pragma unroll
            for (int mi = 0; mi < 2; mi++) {
                int r = (wm << 5) + (mi << 4) + g;
                int kc = ks + (t4 << 1);
                ah[mi][0] = *(unsigned*)&Ah[r][kc];
                ah[mi][1] = *(unsigned*)&Ah[r + 8][kc];
                ah[mi][2] = *(unsigned*)&Ah[r][kc + 8];
                ah[mi][3] = *(unsigned*)&Ah[r + 8][kc + 8];
                al[mi][0] = *(unsigned*)&Al[r][kc];
                al[mi][1] = *(unsigned*)&Al[r + 8][kc];
                al[mi][2] = *(unsigned*)&Al[r][kc + 8];
                al[mi][3] = *(unsigned*)&Al[r + 8][kc + 8];
            }
#pragma unroll
            for (int ni = 0; ni < 8; ni++) {
                int nr = (wn << 6) + (ni << 3) + g;
                int kc = ks + (t4 << 1);
                unsigned bh0 = *(unsigned*)&Bh[nr][kc];
                unsigned bh1 = *(unsigned*)&Bh[nr][kc + 8];
                unsigned bl0 = *(unsigned*)&Bl[nr][kc];
                unsigned bl1 = *(unsigned*)&Bl[nr][kc + 8];
#pragma unroll
                for (int mi = 0; mi < 2; mi++) {
                    mma16816(acc[mi][ni], ah[mi], bh0, bh1);
                    mma16816(acc[mi][ni], al[mi], bh0, bh1);
                    mma16816(acc[mi][ni], ah[mi], bl0, bl1);
                }
            }
        }
        __syncthreads();
    }

    // ---- epilogue ----
#pragma unroll
    for (int mi = 0; mi < 2; mi++) {
#pragma unroll
        for (int ni = 0; ni < 8; ni++) {
            int row = m0 + (wm << 5) + (mi << 4) + g;
            int col = n0 + (wn << 6) + (ni << 3) + (t4 << 1);
            if (col >= N) continue;
            float b0 = 0.f, b1 = 0.f;
            if (bias) { b0 = bias[col]; b1 = bias[col + 1]; }
            if (row < M) {
                float2 v;
                v.x = acc[mi][ni][0] + b0;
                v.y = acc[mi][ni][1] + b1;
                if (do_relu) { v.x = fmaxf(v.x, 0.f); v.y = fmaxf(v.y, 0.f); }
                *(float2*)&C[(size_t)row * ldc + coff + col] = v;
            }
            if (row + 8 < M) {
                float2 v;
                v.x = acc[mi][ni][2] + b0;
                v.y = acc[mi][ni][3] + b1;
                if (do_relu) { v.x = fmaxf(v.x, 0.f); v.y = fmaxf(v.y, 0.f); }
                *(float2*)&C[(size_t)(row + 8) * ldc + coff + col] = v;
            }
        }
    }
}

// ------------------------------ aggregation --------------------------------
template <int V>
__global__ void agg_kernel(const float* __restrict__ Y, int ldy, int ycol,
                           int rcol, const float* __restrict__ bias,
                           float* __restrict__ Out, int ldo, int ocol, int Nn)
{
    int gw = (blockIdx.x * blockDim.x + threadIdx.x) >> 5;
    int lane = threadIdx.x & 31;
    if (gw >= Nn) return;
    int s0 = g_row_off[gw], s1 = g_row_off[gw + 1];
    int col = lane * V;
    float acc[V];
#pragma unroll
    for (int v = 0; v < V; v++) acc[v] = 0.f;
    const float* Yb = Y + ycol + col;

    int j = s0;
    for (; j + 1 < s1; j += 2) {
        int sA = g_src_sorted[j];
        int sB = g_src_sorted[j + 1];
        const float* pA = Yb + (size_t)sA * ldy;
        const float* pB = Yb + (size_t)sB * ldy;
        if (V == 4) {
            float4 a = *(const float4*)pA;
            float4 b = *(const float4*)pB;
            acc[0] += a.x + b.x; acc[1] += a.y + b.y;
            acc[2] += a.z + b.z; acc[3] += a.w + b.w;
        } else {
            float2 a = *(const float2*)pA;
            float2 b = *(const float2*)pB;
            acc[0] += a.x + b.x; acc[1] += a.y + b.y;
        }
    }
    if (j < s1) {
        int sA = g_src_sorted[j];
        const float* pA = Yb + (size_t)sA * ldy;
        if (V == 4) {
            float4 a = *(const float4*)pA;
            acc[0] += a.x; acc[1] += a.y; acc[2] += a.z; acc[3] += a.w;
        } else {
            float2 a = *(const float2*)pA;
            acc[0] += a.x; acc[1] += a.y;
        }
    }
    int deg = s1 - s0;
    float inv = 1.f / (float)(deg > 1 ? deg : 1);
    float o[V];
#pragma unroll
    for (int v = 0; v < V; v++) {
        float r = Y[(size_t)gw * ldy + rcol + col + v];
        float b = bias[col + v];
        o[v] = fmaxf(acc[v] * inv + r + b, 0.f);
    }
    if (V == 4)
        *(float4*)&Out[(size_t)gw * ldo + ocol + col] =
            make_float4(o[0], o[1], o[2], o[3]);
    else
        *(float2*)&Out[(size_t)gw * ldo + ocol + col] =
            make_float2(o[0], o[1]);
}

// ------------------------------- launcher ----------------------------------
extern "C" void kernel_launch(void* const* d_in, const int* in_sizes, int n_in,
                              void* d_out, int out_size)
{
    const float* x   = (const float*)d_in[0];
    const void*  eix = d_in[1];
    const float* Wp  = (const float*)d_in[2];
    const float* bp  = (const float*)d_in[3];
    const float* Wl1 = (const float*)d_in[4];
    const float* bl1 = (const float*)d_in[5];
    const float* Wr1 = (const float*)d_in[6];
    const float* Wl2 = (const float*)d_in[7];
    const float* bl2 = (const float*)d_in[8];
    const float* Wr2 = (const float*)d_in[9];
    const float* Wl3 = (const float*)d_in[10];
    const float* bl3 = (const float*)d_in[11];
    const float* Wr3 = (const float*)d_in[12];

    int N = in_sizes[0] / 64;
    int E = in_sizes[1] / 2;
    float* out = (float*)d_out;

    float *dF, *dY;
    __nv_bfloat16 *dWh, *dWlo;
    cudaGetSymbolAddress((void**)&dF, g_F);
    cudaGetSymbolAddress((void**)&dY, g_Y);
    cudaGetSymbolAddress((void**)&dWh, g_Wh);
    cudaGetSymbolAddress((void**)&dWlo, g_Wlo);

    int nb = (N + SCAN_B - 1) / SCAN_B;
    int mg = (N + 127) / 128;

    // ---- weight conversion (small) ----
    cvt_w_kernel<<<(64 * 64 + 255) / 256, 256>>>(Wp, Wp, 64, 64, 64, WOFF_P);
    cvt_w_kernel<<<(128 * 64 + 255) / 256, 256>>>(Wl1, Wr1, 64, 64, 128, WOFF_1);
    cvt_w_kernel<<<(256 * 128 + 255) / 256, 256>>>(Wl2, Wr2, 128, 128, 256, WOFF_2);
    cvt_w_kernel<<<(256 * 256 + 255) / 256, 256>>>(Wl3, Wr3, 256, 128, 256, WOFF_3);

    // ---- layer-1 GEMMs early (also puts them in the ncu capture window) ----
    gemm_bf16x3_kernel<<<dim3(mg, 1), 256>>>(x, 64, dWh + WOFF_P, dWlo + WOFF_P,
                                             bp, dF, 256, 0, N, 64, 64, 1);
    gemm_bf16x3_kernel<<<dim3(mg, 1), 256>>>(x, 64, dWh + WOFF_1, dWlo + WOFF_1,
                                             nullptr, dY, 256, 0, N, 128, 64, 0);

    // ---- CSR build ----
    detect_kernel<<<1, 32>>>((const unsigned int*)eix);
    zero_cnt<<<(N + 255) / 256, 256>>>(N);
    hist_kernel<<<(E + 255) / 256, 256>>>(eix, E);
    scan_blocks<<<nb, SCAN_B>>>(N);
    scan_bsum<<<1, 32>>>(nb);
    scan_add<<<nb, SCAN_B>>>(N, E);
    scatter_kernel<<<(E + 255) / 256, 256>>>(eix, E);

    // ---- layer 1 aggregation ----
    agg_kernel<2><<<(N + 7) / 8, 256>>>(dY, 256, 0, 64, bl1, dF, 256, 64, N);

    // ---- layer 2 ----  in2 = F[:,0:128]
    gemm_bf16x3_kernel<<<dim3(mg, 2), 256>>>(dF, 256, dWh + WOFF_2,
                                             dWlo + WOFF_2, nullptr,
                                             dY, 256, 0, N, 256, 128, 0);
    agg_kernel<4><<<(N + 7) / 8, 256>>>(dY, 256, 0, 128, bl2, dF, 256, 128, N);

    // ---- layer 3 ----  in3 = F[:,0:256]
    gemm_bf16x3_kernel<<<dim3(mg, 2), 256>>>(dF, 256, dWh + WOFF_3,
                                             dWlo + WOFF_3, nullptr,
                                             dY, 256, 0, N, 256, 256, 0);
    agg_kernel<4><<<(N + 7) / 8, 256>>>(dY, 256, 0, 128, bl3, out, 128, 0, N);
}

// round 5
// speedup vs baseline: 1.8173x; 1.2758x over previous
#include <cuda_runtime.h>
#include <cuda_bf16.h>
#include <cstdint>

// ---------------------------------------------------------------------------
// DenseGCN (3-layer GraphSAGE, mean aggr) on GB300.
//   - matmul BEFORE mean-aggregation (linearity).
//   - CSR build, gather-side aggregation (no float atomics).
//   - GEMMs: bf16 mma.sync m16n8k16 with 3-term hi/lo split (err ~1e-5),
//     cp.async double-buffered staging + ldmatrix fragment loads.
//   - activations stored pre-split (bf16 hi/lo) by agg/epilogues.
// ---------------------------------------------------------------------------

#define NMAX 50176
#define EMAX 1000448
#define SCAN_B 1024

__device__ __align__(16) float g_Y[(size_t)NMAX * 256];           // GEMM outputs (fp32)
__device__ __align__(16) __nv_bfloat16 g_Xh[(size_t)NMAX * 64];   // x split
__device__ __align__(16) __nv_bfloat16 g_Xl[(size_t)NMAX * 64];
__device__ __align__(16) __nv_bfloat16 g_Fh[(size_t)NMAX * 256];  // activations split
__device__ __align__(16) __nv_bfloat16 g_Fl[(size_t)NMAX * 256];
__device__ __align__(16) __nv_bfloat16 g_Wh[110592];
__device__ __align__(16) __nv_bfloat16 g_Wlo[110592];
__device__ int g_row_off[NMAX + 1];
__device__ int g_cnt[NMAX];
__device__ int g_bsum[64];
__device__ int g_src_sorted[EMAX];
__device__ int g_is64;

#define WOFF_P 0
#define WOFF_1 4096
#define WOFF_2 12288
#define WOFF_3 45056

// --------------------------- PTX helpers -----------------------------------
__device__ __forceinline__ void ldm4(unsigned* r, uint32_t addr) {
    asm volatile("ldmatrix.sync.aligned.m8n8.x4.shared.b16 {%0,%1,%2,%3}, [%4];"
                 : "=r"(r[0]), "=r"(r[1]), "=r"(r[2]), "=r"(r[3]) : "r"(addr));
}
__device__ __forceinline__ void cp16(uint32_t d, const void* s, bool p) {
    asm volatile("cp.async.cg.shared.global [%0], [%1], 16, %2;"
                 :: "r"(d), "l"(s), "r"(p ? 16 : 0) : "memory");
}
__device__ __forceinline__ void cpcommit() {
    asm volatile("cp.async.commit_group;" ::: "memory");
}
__device__ __forceinline__ void mma16816(float* c, const unsigned* a,
                                         unsigned b0, unsigned b1) {
    asm volatile(
        "mma.sync.aligned.m16n8k16.row.col.f32.bf16.bf16.f32 "
        "{%0,%1,%2,%3}, {%4,%5,%6,%7}, {%8,%9}, {%0,%1,%2,%3};"
        : "+f"(c[0]), "+f"(c[1]), "+f"(c[2]), "+f"(c[3])
        : "r"(a[0]), "r"(a[1]), "r"(a[2]), "r"(a[3]), "r"(b0), "r"(b1));
}

// --------------------------- edge dtype detection --------------------------
__global__ void detect_kernel(const unsigned int* e) {
    if (threadIdx.x == 0) {
        int is64 = 1;
        for (int i = 0; i < 8; i++)
            if (e[2 * i + 1] != 0u) is64 = 0;
        g_is64 = is64;
    }
}

__global__ void zero_cnt(int n) {
    int i = blockIdx.x * blockDim.x + threadIdx.x;
    if (i < n) g_cnt[i] = 0;
}

__global__ void hist_kernel(const void* e, int E) {
    int i = blockIdx.x * blockDim.x + threadIdx.x;
    if (i >= E) return;
    int dst;
    if (g_is64) dst = (int)((const long long*)e)[(size_t)E + i];
    else        dst = ((const int*)e)[E + i];
    atomicAdd(&g_cnt[dst], 1);
}

__global__ void __launch_bounds__(SCAN_B) scan_blocks(int n) {
    __shared__ int wsum[32];
    int tid = threadIdx.x;
    int lane = tid & 31, wid = tid >> 5;
    int i = blockIdx.x * SCAN_B + tid;
    int v = (i < n) ? g_cnt[i] : 0;
    int incl = v;
#pragma unroll
    for (int off = 1; off < 32; off <<= 1) {
        int t = __shfl_up_sync(0xffffffffu, incl, off);
        if (lane >= off) incl += t;
    }
    if (lane == 31) wsum[wid] = incl;
    __syncthreads();
    if (wid == 0) {
        int w = wsum[lane];
#pragma unroll
        for (int off = 1; off < 32; off <<= 1) {
            int t = __shfl_up_sync(0xffffffffu, w, off);
            if (lane >= off) w += t;
        }
        wsum[lane] = w;
    }
    __syncthreads();
    int add = (wid > 0) ? wsum[wid - 1] : 0;
    int excl = add + incl - v;
    if (i < n) g_row_off[i] = excl;
    if (tid == SCAN_B - 1) g_bsum[blockIdx.x] = add + incl;
}

__global__ void scan_bsum(int nb) {
    if (threadIdx.x == 0) {
        int run = 0;
        for (int b = 0; b < nb; b++) {
            int t = g_bsum[b];
            g_bsum[b] = run;
            run += t;
        }
    }
}

__global__ void __launch_bounds__(SCAN_B) scan_add(int n, int E) {
    int i = blockIdx.x * SCAN_B + threadIdx.x;
    if (i < n) {
        int v = g_row_off[i] + g_bsum[blockIdx.x];
        g_row_off[i] = v;
        g_cnt[i] = v;
    }
    if (blockIdx.x == 0 && threadIdx.x == 0) g_row_off[n] = E;
}

__global__ void scatter_kernel(const void* e, int E) {
    int i = blockIdx.x * blockDim.x + threadIdx.x;
    if (i >= E) return;
    int src, dst;
    if (g_is64) {
        src = (int)((const long long*)e)[i];
        dst = (int)((const long long*)e)[(size_t)E + i];
    } else {
        src = ((const int*)e)[i];
        dst = ((const int*)e)[E + i];
    }
    int pos = atomicAdd(&g_cnt[dst], 1);
    g_src_sorted[pos] = src;
}

// ---------------- weight conversion (all layers, one kernel) ---------------
__global__ void cvt_w_all(const float* __restrict__ Wp,
                          const float* __restrict__ Wl1, const float* __restrict__ Wr1,
                          const float* __restrict__ Wl2, const float* __restrict__ Wr2,
                          const float* __restrict__ Wl3, const float* __restrict__ Wr3) {
    int i = blockIdx.x * blockDim.x + threadIdx.x;
    if (i >= 110592) return;
    const float *L, *R;
    int K, Fo, base;
    if (i < 12288) {
        if (i < 4096) { base = WOFF_P; K = 64; Fo = 64; L = Wp;  R = Wp; }
        else          { base = WOFF_1; K = 64; Fo = 64; L = Wl1; R = Wr1; }
    } else if (i < 45056) { base = WOFF_2; K = 128; Fo = 128; L = Wl2; R = Wr2; }
    else                  { base = WOFF_3; K = 256; Fo = 128; L = Wl3; R = Wr3; }
    int j = i - base;
    int n = j / K, k = j % K;
    float w = (n < Fo) ? L[k * Fo + n] : R[k * Fo + (n - Fo)];
    __nv_bfloat16 hi = __float2bfloat16_rn(w);
    g_Wh[i]  = hi;
    g_Wlo[i] = __float2bfloat16_rn(w - __bfloat162float(hi));
}

// ------------------------- x split: fp32 -> hi/lo --------------------------
__global__ void cvt_x_kernel(const float* __restrict__ x, int n) {
    int i = blockIdx.x * blockDim.x + threadIdx.x;
    if (i >= n) return;
    float v = x[i];
    __nv_bfloat16 hi = __float2bfloat16_rn(v);
    g_Xh[i] = hi;
    g_Xl[i] = __float2bfloat16_rn(v - __bfloat162float(hi));
}

// --------------------------- tensor-core GEMM ------------------------------
// C = A @ W, A given as bf16 hi/lo [M][lda], W as bf16 hi/lo [N][K].
// Block tile 128x128, 8 warps (4m x 2n), warp tile 32x64, m16n8k16 mma.
// K multiple of 32. cp.async double-buffered staging, ldmatrix frags.
// Output: if Cf != null -> fp32 (no bias/relu opts as flags), else split
// bf16 hi/lo to Ch/Cl.
#define SROWB 80
#define ARRB  10240
#define STAGEB 40960
#define GEMM_SMEM (2 * STAGEB)

__global__ void __launch_bounds__(256) gemm_tc_kernel(
    const __nv_bfloat16* __restrict__ Ahg, const __nv_bfloat16* __restrict__ Alg,
    int lda,
    const __nv_bfloat16* __restrict__ Wh, const __nv_bfloat16* __restrict__ Wl,
    const float* __restrict__ bias,
    float* __restrict__ Cf, __nv_bfloat16* __restrict__ Ch,
    __nv_bfloat16* __restrict__ Cl,
    int ldc, int coff, int M, int N, int K, int do_relu)
{
    extern __shared__ __align__(16) char smem_raw[];
    uint32_t sb0 = (uint32_t)__cvta_generic_to_shared(smem_raw);
    int tid = threadIdx.x, lane = tid & 31, wid = tid >> 5;
    int wm = wid & 3, wn = wid >> 2;
    int g = lane >> 2, t4 = lane & 3;
    int m0 = blockIdx.x << 7, n0 = blockIdx.y << 7;

    uint32_t arowoff[2];
#pragma unroll
    for (int mi = 0; mi < 2; mi++) {
        int r = (wm << 5) + (mi << 4) + (lane & 7) + (((lane >> 3) & 1) << 3);
        arowoff[mi] = (uint32_t)r * SROWB + ((lane >> 4) << 4);
    }
    uint32_t boff[4];
#pragma unroll
    for (int p = 0; p < 4; p++) {
        int r = (wn << 6) + (p << 4) + (lane & 7) + ((lane >> 4) << 3);
        boff[p] = (uint32_t)r * SROWB + (((lane >> 3) & 1) << 4);
    }

    float acc[2][8][4];
#pragma unroll
    for (int mi = 0; mi < 2; mi++)
#pragma unroll
        for (int ni = 0; ni < 8; ni++)
#pragma unroll
            for (int q = 0; q < 4; q++) acc[mi][ni][q] = 0.f;

    auto stage = [&](int kt, int s) {
        int k0 = kt << 5;
        uint32_t sb = sb0 + (uint32_t)s * STAGEB;
#pragma unroll
        for (int h = 0; h < 2; h++) {
            int c = tid + (h << 8);
            int row = c >> 2, part = c & 3;
            uint32_t soff = (uint32_t)row * SROWB + (part << 4);
            int am = m0 + row;
            bool av = am < M; if (!av) am = 0;
            size_t aoff = (size_t)am * lda + k0 + (part << 3);
            cp16(sb + soff,            Ahg + aoff, av);
            cp16(sb + ARRB + soff,     Alg + aoff, av);
            int bn = n0 + row;
            bool bv = bn < N; if (!bv) bn = 0;
            size_t woff = (size_t)bn * K + k0 + (part << 3);
            cp16(sb + 2 * ARRB + soff, Wh + woff, bv);
            cp16(sb + 3 * ARRB + soff, Wl + woff, bv);
        }
        cpcommit();
    };

    int KT = K >> 5;
    stage(0, 0);
    for (int kt = 0; kt < KT; kt++) {
        int s = kt & 1;
        if (kt + 1 < KT) {
            stage(kt + 1, s ^ 1);
            asm volatile("cp.async.wait_group 1;" ::: "memory");
        } else {
            asm volatile("cp.async.wait_group 0;" ::: "memory");
        }
        __syncthreads();
        uint32_t sb = sb0 + (uint32_t)s * STAGEB;
#pragma unroll
        for (int ks = 0; ks < 2; ks++) {
            uint32_t ko = (uint32_t)ks << 5;
            unsigned ah[2][4], al[2][4];
            ldm4(ah[0], sb + arowoff[0] + ko);
            ldm4(ah[1], sb + arowoff[1] + ko);
            ldm4(al[0], sb + ARRB + arowoff[0] + ko);
            ldm4(al[1], sb + ARRB + arowoff[1] + ko);
#pragma unroll
            for (int p = 0; p < 4; p++) {
                unsigned bh[4], bl[4];
                ldm4(bh, sb + 2 * ARRB + boff[p] + ko);
                ldm4(bl, sb + 3 * ARRB + boff[p] + ko);
#pragma unroll
                for (int mi = 0; mi < 2; mi++) {
                    mma16816(acc[mi][2 * p],     ah[mi], bh[0], bh[1]);
                    mma16816(acc[mi][2 * p],     al[mi], bh[0], bh[1]);
                    mma16816(acc[mi][2 * p],     ah[mi], bl[0], bl[1]);
                    mma16816(acc[mi][2 * p + 1], ah[mi], bh[2], bh[3]);
                    mma16816(acc[mi][2 * p + 1], al[mi], bh[2], bh[3]);
                    mma16816(acc[mi][2 * p + 1], ah[mi], bl[2], bl[3]);
                }
            }
        }
        __syncthreads();
    }

    // ---- epilogue ----
#pragma unroll
    for (int mi = 0; mi < 2; mi++) {
#pragma unroll
        for (int ni = 0; ni < 8; ni++) {
            int row = m0 + (wm << 5) + (mi << 4) + g;
            int col = n0 + (wn << 6) + (ni << 3) + (t4 << 1);
            if (col >= N) continue;
            float b0 = 0.f, b1 = 0.f;
            if (bias) { b0 = bias[col]; b1 = bias[col + 1]; }
#pragma unroll
            for (int hh = 0; hh < 2; hh++) {
                int r = row + hh * 8;
                if (r >= M) continue;
                float vx = acc[mi][ni][2 * hh]     + b0;
                float vy = acc[mi][ni][2 * hh + 1] + b1;
                if (do_relu) { vx = fmaxf(vx, 0.f); vy = fmaxf(vy, 0.f); }
                size_t off = (size_t)r * ldc + coff + col;
                if (Cf) {
                    *(float2*)&Cf[off] = make_float2(vx, vy);
                } else {
                    __nv_bfloat16 hx = __float2bfloat16_rn(vx);
                    __nv_bfloat16 hy = __float2bfloat16_rn(vy);
                    __nv_bfloat16 lx =
                        __float2bfloat16_rn(vx - __bfloat162float(hx));
                    __nv_bfloat16 ly =
                        __float2bfloat16_rn(vy - __bfloat162float(hy));
                    *(__nv_bfloat162*)&Ch[off] = __halves2bfloat162(hx, hy);
                    *(__nv_bfloat162*)&Cl[off] = __halves2bfloat162(lx, ly);
                }
            }
        }
    }
}

// ------------------------------ aggregation --------------------------------
// out = relu(mean_j Y[src_j, ycol:] + Y[n, rcol:] + bias).
// If Oh != null: write bf16 hi/lo split to Oh/Ol, else fp32 to Of.
template <int V>
__global__ void agg_kernel(const float* __restrict__ Y, int ldy, int ycol,
                           int rcol, const float* __restrict__ bias,
                           float* __restrict__ Of,
                           __nv_bfloat16* __restrict__ Oh,
                           __nv_bfloat16* __restrict__ Ol,
                           int ldo, int ocol, int Nn)
{
    int gw = (blockIdx.x * blockDim.x + threadIdx.x) >> 5;
    int lane = threadIdx.x & 31;
    if (gw >= Nn) return;
    int s0 = g_row_off[gw], s1 = g_row_off[gw + 1];
    int col = lane * V;
    float acc[V];
#pragma unroll
    for (int v = 0; v < V; v++) acc[v] = 0.f;
    const float* Yb = Y + ycol + col;

    int j = s0;
    for (; j + 1 < s1; j += 2) {
        int sA = g_src_sorted[j];
        int sB = g_src_sorted[j + 1];
        const float* pA = Yb + (size_t)sA * ldy;
        const float* pB = Yb + (size_t)sB * ldy;
        if (V == 4) {
            float4 a = *(const float4*)pA;
            float4 b = *(const float4*)pB;
            acc[0] += a.x + b.x; acc[1] += a.y + b.y;
            acc[2] += a.z + b.z; acc[3] += a.w + b.w;
        } else {
            float2 a = *(const float2*)pA;
            float2 b = *(const float2*)pB;
            acc[0] += a.x + b.x; acc[1] += a.y + b.y;
        }
    }
    if (j < s1) {
        int sA = g_src_sorted[j];
        const float* pA = Yb + (size_t)sA * ldy;
        if (V == 4) {
            float4 a = *(const float4*)pA;
            acc[0] += a.x; acc[1] += a.y; acc[2] += a.z; acc[3] += a.w;
        } else {
            float2 a = *(const float2*)pA;
            acc[0] += a.x; acc[1] += a.y;
        }
    }
    int deg = s1 - s0;
    float inv = 1.f / (float)(deg > 1 ? deg : 1);
    float o[V];
#pragma unroll
    for (int v = 0; v < V; v++) {
        float r = Y[(size_t)gw * ldy + rcol + col + v];
        float b = bias[col + v];
        o[v] = fmaxf(acc[v] * inv + r + b, 0.f);
    }
    size_t off = (size_t)gw * ldo + ocol + col;
    if (Oh) {
#pragma unroll
        for (int v = 0; v < V; v += 2) {
            __nv_bfloat16 h0 = __float2bfloat16_rn(o[v]);
            __nv_bfloat16 h1 = __float2bfloat16_rn(o[v + 1]);
            __nv_bfloat16 l0 =
                __float2bfloat16_rn(o[v] - __bfloat162float(h0));
            __nv_bfloat16 l1 =
                __float2bfloat16_rn(o[v + 1] - __bfloat162float(h1));
            *(__nv_bfloat162*)&Oh[off + v] = __halves2bfloat162(h0, h1);
            *(__nv_bfloat162*)&Ol[off + v] = __halves2bfloat162(l0, l1);
        }
    } else {
        if (V == 4)
            *(float4*)&Of[off] = make_float4(o[0], o[1], o[2], o[3]);
        else
            *(float2*)&Of[off] = make_float2(o[0], o[1]);
    }
}

// ------------------------------- launcher ----------------------------------
extern "C" void kernel_launch(void* const* d_in, const int* in_sizes, int n_in,
                              void* d_out, int out_size)
{
    const float* x   = (const float*)d_in[0];
    const void*  eix = d_in[1];
    const float* Wp  = (const float*)d_in[2];
    const float* bp  = (const float*)d_in[3];
    const float* Wl1 = (const float*)d_in[4];
    const float* bl1 = (const float*)d_in[5];
    const float* Wr1 = (const float*)d_in[6];
    const float* Wl2 = (const float*)d_in[7];
    const float* bl2 = (const float*)d_in[8];
    const float* Wr2 = (const float*)d_in[9];
    const float* Wl3 = (const float*)d_in[10];
    const float* bl3 = (const float*)d_in[11];
    const float* Wr3 = (const float*)d_in[12];

    int N = in_sizes[0] / 64;
    int E = in_sizes[1] / 2;
    float* out = (float*)d_out;

    float* dY;
    __nv_bfloat16 *dXh, *dXl, *dFh, *dFl, *dWh, *dWlo;
    cudaGetSymbolAddress((void**)&dY, g_Y);
    cudaGetSymbolAddress((void**)&dXh, g_Xh);
    cudaGetSymbolAddress((void**)&dXl, g_Xl);
    cudaGetSymbolAddress((void**)&dFh, g_Fh);
    cudaGetSymbolAddress((void**)&dFl, g_Fl);
    cudaGetSymbolAddress((void**)&dWh, g_Wh);
    cudaGetSymbolAddress((void**)&dWlo, g_Wlo);

    cudaFuncSetAttribute(gemm_tc_kernel,
                         cudaFuncAttributeMaxDynamicSharedMemorySize,
                         GEMM_SMEM);

    int nb = (N + SCAN_B - 1) / SCAN_B;
    int mg = (N + 127) / 128;

    // ---- conversions ----
    cvt_w_all<<<(110592 + 255) / 256, 256>>>(Wp, Wl1, Wr1, Wl2, Wr2, Wl3, Wr3);
    cvt_x_kernel<<<(N * 64 + 255) / 256, 256>>>(x, N * 64);

    // ---- layer-1 GEMMs ----
    // x_p = relu(x@Wp+bp) -> Fh/Fl[:,0:64]
    gemm_tc_kernel<<<dim3(mg, 1), 256, GEMM_SMEM>>>(
        dXh, dXl, 64, dWh + WOFF_P, dWlo + WOFF_P, bp,
        nullptr, dFh, dFl, 256, 0, N, 64, 64, 1);
    // [y1 | r1] = x@[Wl1|Wr1] -> Y[:,0:128]
    gemm_tc_kernel<<<dim3(mg, 1), 256, GEMM_SMEM>>>(
        dXh, dXl, 64, dWh + WOFF_1, dWlo + WOFF_1, nullptr,
        dY, nullptr, nullptr, 256, 0, N, 128, 64, 0);

    // ---- CSR build ----
    detect_kernel<<<1, 32>>>((const unsigned int*)eix);
    zero_cnt<<<(N + 255) / 256, 256>>>(N);
    hist_kernel<<<(E + 255) / 256, 256>>>(eix, E);
    scan_blocks<<<nb, SCAN_B>>>(N);
    scan_bsum<<<1, 32>>>(nb);
    scan_add<<<nb, SCAN_B>>>(N, E);
    scatter_kernel<<<(E + 255) / 256, 256>>>(eix, E);

    // ---- layer 1 aggregation -> Fh/Fl[:,64:128] ----
    agg_kernel<2><<<(N + 7) / 8, 256>>>(dY, 256, 0, 64, bl1,
                                        nullptr, dFh, dFl, 256, 64, N);

    // ---- layer 2 ----
    gemm_tc_kernel<<<dim3(mg, 2), 256, GEMM_SMEM>>>(
        dFh, dFl, 256, dWh + WOFF_2, dWlo + WOFF_2, nullptr,
        dY, nullptr, nullptr, 256, 0, N, 256, 128, 0);
    agg_kernel<4><<<(N + 7) / 8, 256>>>(dY, 256, 0, 128, bl2,
                                        nullptr, dFh, dFl, 256, 128, N);

    // ---- layer 3 ----
    gemm_tc_kernel<<<dim3(mg, 2), 256, GEMM_SMEM>>>(
        dFh, dFl, 256, dWh + WOFF_3, dWlo + WOFF_3, nullptr,
        dY, nullptr, nullptr, 256, 0, N, 256, 256, 0);
    agg_kernel<4><<<(N + 7) / 8, 256>>>(dY, 256, 0, 128, bl3,
                                        out, nullptr, nullptr, 128, 0, N);
}